// round 8
// baseline (speedup 1.0000x reference)
#include <cuda_runtime.h>

#define BATCH   64
#define HW      5456
#define NCH     85
#define NCLS    80
#define NTOP    100
#define PER_IMG (HW * NCH)        /* 463760 floats per image */
#define T_CAND  2.0f
#define T_CHECK 2.73f
#define FLATMAX 524287            /* 2^19 - 1; flat = c*HW+hw < 436480 */

#define SEGS    16                /* filter blocks per image */
#define SEG_ROWS (HW / SEGS)      /* 341 */
#define SEGCAP  2048              /* slots per segment (power of 2) */
#define NSLOT   (SEGS * SEGCAP)   /* 32768 slots per image */
#define SKEYMAX 12288             /* dynamic-smem key capacity in k_topk_nms */

// Scratch (static device globals: allowed; runtime allocation is not).
// Per-segment buffers written unconditionally every launch -> no reset kernel,
// no global atomics anywhere.
__device__ unsigned long long g_cand[BATCH][NSLOT];   // 16 MB
__device__ int g_scnt[BATCH][SEGS];
__device__ int g_ssafe[BATCH][SEGS];

// ---------------------------------------------------------------------------
// Bit-exact XLA-style sigmoid: 1 / (1 + expf(-x)), div.rn, no contraction.
__device__ __forceinline__ float xla_sigmoid(float x) {
    return __fdiv_rn(1.0f, __fadd_rn(1.0f, expf(-x)));
}

__device__ __forceinline__ unsigned long long make_key(float score, int flat) {
    // score in (0,1): positive float bits are order-preserving as uint.
    // Larger key = better: score desc, then smaller flat index (class-major).
    return ((unsigned long long)__float_as_uint(score) << 19)
         | (unsigned)(FLATMAX - flat);
}

// ---------------------------------------------------------------------------
// Kernel 1: stream all logits; for candidate cls logits (>= T_CAND) compute
// the FINAL composite key (sigmoid^pow score) right here -- nks (ch 84) is
// already in-register -- and stage keys in smem. One deterministic slot range
// per block; counts stored unconditionally (no atomics, no reset).
__global__ void __launch_bounds__(256) k_filter(const float* __restrict__ pred) {
    __shared__ unsigned long long s_buf[SEGCAP];
    __shared__ int s_cnt, s_safe;

    const int b    = blockIdx.x / SEGS;
    const int seg  = blockIdx.x % SEGS;
    const int lane = threadIdx.x & 31;
    const int warp = threadIdx.x >> 5;

    if (threadIdx.x == 0) { s_cnt = 0; s_safe = 0; }
    __syncthreads();

    const int lr0 = warp * 43;
    const int lr1 = min(lr0 + 43, SEG_ROWS);
    const float* imgBase = pred + (size_t)b * PER_IMG;

    int safeAcc = 0;
    for (int lr = lr0; lr < lr1; ++lr) {
        const int hw = seg * SEG_ROWS + lr;
        const float* row = imgBase + (size_t)hw * NCH;
        float v0 = row[lane];           // channels 0..31
        float v1 = row[lane + 32];      // channels 32..63
        float v2 = (lane < 21) ? row[lane + 64] : -1e30f;  // channels 64..84
        float nks = __shfl_sync(0xFFFFFFFFu, v2, 20);      // channel 84
        bool p0 = v0 >= T_CAND;
        bool p1 = v1 >= T_CAND;
        bool p2 = (lane < 16) && (v2 >= T_CAND);  // only ch 64..79 are cls
        unsigned m0 = __ballot_sync(0xFFFFFFFFu, p0);
        unsigned m1 = __ballot_sync(0xFFFFFFFFu, p1);
        unsigned m2 = __ballot_sync(0xFFFFFFFFu, p2);
        if (m0 | m1 | m2) {
            // Exponent shared by every candidate in this row.
            float e = __fsub_rn(2.0f, xla_sigmoid(nks));
            int tot = __popc(m0) + __popc(m1) + __popc(m2);
            int base;
            if (lane == 0) base = atomicAdd(&s_cnt, tot);   // smem atomic
            base = __shfl_sync(0xFFFFFFFFu, base, 0);
            unsigned lt = (1u << lane) - 1u;
            if (p0) {
                float sc = powf(xla_sigmoid(v0), e);
                int o = base + __popc(m0 & lt);
                if (o < SEGCAP) s_buf[o] = make_key(sc, lane * HW + hw);
            }
            int b1 = base + __popc(m0);
            if (p1) {
                float sc = powf(xla_sigmoid(v1), e);
                int o = b1 + __popc(m1 & lt);
                if (o < SEGCAP) s_buf[o] = make_key(sc, (lane + 32) * HW + hw);
            }
            int b2 = b1 + __popc(m1);
            if (p2) {
                float sc = powf(xla_sigmoid(v2), e);
                int o = b2 + __popc(m2 & lt);
                if (o < SEGCAP) s_buf[o] = make_key(sc, (lane + 64) * HW + hw);
            }
            safeAcc += (int)(p0 && v0 >= T_CHECK)
                     + (int)(p1 && v1 >= T_CHECK)
                     + (int)(p2 && v2 >= T_CHECK);
        }
    }
    {   // warp-reduce safe count -> one smem atomic per warp
        int s = safeAcc;
        s += __shfl_xor_sync(0xFFFFFFFFu, s, 16);
        s += __shfl_xor_sync(0xFFFFFFFFu, s, 8);
        s += __shfl_xor_sync(0xFFFFFFFFu, s, 4);
        s += __shfl_xor_sync(0xFFFFFFFFu, s, 2);
        s += __shfl_xor_sync(0xFFFFFFFFu, s, 1);
        if (lane == 0 && s) atomicAdd(&s_safe, s);
    }
    __syncthreads();

    // Unconditional deterministic writes: this block owns its slot range.
    if (threadIdx.x == 0) {
        g_scnt[b][seg]  = (s_cnt > SEGCAP) ? -1 : s_cnt;  // -1 => fallback
        g_ssafe[b][seg] = s_safe;
    }
    int total = min(s_cnt, SEGCAP);
    unsigned long long* dst = &g_cand[b][seg * SEGCAP];
    for (int i = threadIdx.x; i < total; i += 256) dst[i] = s_buf[i];
}

// ---------------------------------------------------------------------------
// Kernel 2: one block per image. Keys are already final. Stage them into
// dynamic smem once, radix-select the exact 100th key (warp-parallel
// suffix-scan per pass), sort top-100, decode boxes, class-aware NMS, write.
__global__ void __launch_bounds__(512) k_topk_nms(const float* __restrict__ pred,
                                                  const float* __restrict__ pixloc,
                                                  float* __restrict__ out) {
    extern __shared__ unsigned long long s_keys[];   // SKEYMAX entries
    const int b = blockIdx.x;
    const int tid = threadIdx.x;
    const int NT = 512;

    __shared__ int s_hist[256];
    __shared__ int s_ssum[256];
    __shared__ int s_c[SEGS], s_off[SEGS];
    __shared__ unsigned long long s_prefix;
    __shared__ int s_rank, s_n, s_cnt;
    __shared__ unsigned long long s_top[128];
    __shared__ float s_x1[NTOP], s_y1[NTOP], s_x2[NTOP], s_y2[NTOP];
    __shared__ float s_area[NTOP], s_sc[NTOP];
    __shared__ int s_cls[NTOP];
    __shared__ unsigned s_supp[NTOP][4];
    __shared__ unsigned s_keep[4];

    const float* base = pred + (size_t)b * PER_IMG;

    if (tid < SEGS) s_c[tid] = g_scnt[b][tid];
    __syncthreads();

    if (tid == 0) {
        int total = 0, safe = 0;
        bool bad = false;
        for (int s = 0; s < SEGS; ++s) {
            int c = s_c[s];
            if (c < 0) bad = true;
            s_off[s] = total;
            total += max(c, 0);
            safe += g_ssafe[b][s];
        }
        if (!bad && total <= SKEYMAX && total >= NTOP && safe >= NTOP) {
            s_n = total;
        } else {
            // Brute-force fallback (correct for any data; never expected).
            unsigned long long best[NTOP];
            int nb = 0, minidx = 0;
            unsigned long long minkey = 0;
            for (int hw = 0; hw < HW; ++hw) {
                float e = __fsub_rn(2.0f, xla_sigmoid(base[hw * NCH + NCLS + 4]));
                for (int c = 0; c < NCLS; ++c) {
                    float s = xla_sigmoid(base[hw * NCH + c]);
                    if (nb == NTOP &&
                        __float_as_uint(s) < (unsigned)(minkey >> 19)) continue;
                    float sc = powf(s, e);
                    unsigned long long key = make_key(sc, c * HW + hw);
                    if (nb < NTOP) {
                        best[nb++] = key;
                        if (nb == NTOP) {
                            minkey = best[0]; minidx = 0;
                            for (int i = 1; i < NTOP; ++i)
                                if (best[i] < minkey) { minkey = best[i]; minidx = i; }
                        }
                    } else if (key > minkey) {
                        best[minidx] = key;
                        minkey = best[0]; minidx = 0;
                        for (int i = 1; i < NTOP; ++i)
                            if (best[i] < minkey) { minkey = best[i]; minidx = i; }
                    }
                }
            }
            for (int i = 0; i < NTOP; ++i) s_keys[i] = best[i];
            s_n = -NTOP;   // negative => keys already staged in s_keys
        }
        s_prefix = 0ULL;
        s_rank = NTOP;
        s_cnt = 0;
    }
    __syncthreads();

    int n = s_n;
    if (n >= 0) {
        // Stage all candidate keys into smem (coalesced per segment).
        for (int s = 0; s < SEGS; ++s) {
            int c = s_c[s], off = s_off[s];
            const unsigned long long* src = &g_cand[b][s * SEGCAP];
            for (int i = tid; i < c; i += NT) s_keys[off + i] = src[i];
        }
    } else {
        n = -n;
    }
    __syncthreads();

    // Phase 2: MSB radix-select the exact 100th-largest key (keys unique).
    unsigned long long prefix = 0ULL;
    for (int d = 6; d >= 0; --d) {
        int rank = s_rank;
        if (tid < 256) s_hist[tid] = 0;
        __syncthreads();
        unsigned long long hmask = (~0ULL) << (8 * (d + 1));
        for (int i = tid; i < n; i += NT) {
            unsigned long long k = s_keys[i];
            if (((k ^ prefix) & hmask) == 0ULL)
                atomicAdd(&s_hist[(int)((k >> (8 * d)) & 255)], 1);
        }
        __syncthreads();
        // Warp-parallel suffix sums: s_ssum[v] = sum(hist[v..255]).
        if (tid < 32) {
            int loc[8]; int sum = 0;
            #pragma unroll
            for (int j = 0; j < 8; ++j) {
                sum += s_hist[255 - (tid * 8 + j)];
                loc[j] = sum;
            }
            int inc = sum;
            #pragma unroll
            for (int dd = 1; dd < 32; dd <<= 1) {
                int y = __shfl_up_sync(0xFFFFFFFFu, inc, dd);
                if (tid >= dd) inc += y;
            }
            int excl = inc - sum;
            #pragma unroll
            for (int j = 0; j < 8; ++j)
                s_ssum[255 - (tid * 8 + j)] = excl + loc[j];
        }
        __syncthreads();
        if (tid < 256) {
            int above = (tid < 255) ? s_ssum[tid + 1] : 0;
            if (s_ssum[tid] >= rank && above < rank) {   // unique tid
                s_rank = rank - above;
                s_prefix = prefix | ((unsigned long long)tid << (8 * d));
            }
        }
        __syncthreads();
        prefix = s_prefix;
    }
    unsigned long long kth = prefix;

    // Phase 3: compact the exactly-100 keys >= kth.
    for (int i = tid; i < n; i += NT) {
        unsigned long long k = s_keys[i];
        if (k >= kth) {
            int p = atomicAdd(&s_cnt, 1);
            if (p < 128) s_top[p] = k;
        }
    }
    __syncthreads();
    if (tid < 128 && tid >= s_cnt) s_top[tid] = 0ULL;
    __syncthreads();

    // Phase 4: bitonic sort 128 keys descending.
    for (int k = 2; k <= 128; k <<= 1) {
        for (int j = k >> 1; j > 0; j >>= 1) {
            if (tid < 128) {
                int ixj = tid ^ j;
                if (ixj > tid) {
                    unsigned long long a = s_top[tid], c = s_top[ixj];
                    bool up = (tid & k) == 0;  // descending
                    if (up ? (a < c) : (a > c)) { s_top[tid] = c; s_top[ixj] = a; }
                }
            }
            __syncthreads();
        }
    }

    // Phase 5: decode boxes for the top-100 (bit-exact: no FMA contraction).
    if (tid < NTOP) {
        unsigned long long key = s_top[tid];
        int flat = FLATMAX - (int)(key & 0x7FFFF);
        int c = flat / HW;
        int hw = flat - c * HW;
        float sc = __uint_as_float((unsigned)(key >> 19));
        const float* rp = base + hw * NCH;
        float e0 = expf(rp[80]);
        float e1 = expf(rp[81]);
        float e2 = expf(rp[82]);
        float e3 = expf(rp[83]);
        float x1 = __fadd_rn(__fmul_rn(e0, -1.0f), pixloc[4 * hw + 0]);
        float y1 = __fadd_rn(__fmul_rn(e1, -1.0f), pixloc[4 * hw + 1]);
        float x2 = __fadd_rn(__fmul_rn(e2,  1.0f), pixloc[4 * hw + 2]);
        float y2 = __fadd_rn(__fmul_rn(e3,  1.0f), pixloc[4 * hw + 3]);
        s_x1[tid] = x1; s_y1[tid] = y1; s_x2[tid] = x2; s_y2[tid] = y2;
        s_area[tid] = __fmul_rn(__fsub_rn(x2, x1), __fsub_rn(y2, y1));
        s_sc[tid] = sc;
        s_cls[tid] = c;
    }
    if (tid < NTOP * 4) ((unsigned*)s_supp)[tid] = 0u;
    __syncthreads();

    // Phase 6: suppress matrix (iou > 0.5, same class, j later than i).
    for (int p = tid; p < NTOP * NTOP; p += NT) {
        int i = p / NTOP, j = p - i * NTOP;
        if (j > i && s_cls[i] == s_cls[j]) {
            float xx1 = fmaxf(s_x1[i], s_x1[j]);
            float yy1 = fmaxf(s_y1[i], s_y1[j]);
            float xx2 = fminf(s_x2[i], s_x2[j]);
            float yy2 = fminf(s_y2[i], s_y2[j]);
            float w = fmaxf(1e-28f, __fsub_rn(xx2, xx1));
            float h = fmaxf(1e-28f, __fsub_rn(yy2, yy1));
            float inter = __fmul_rn(w, h);
            float iou = __fdiv_rn(inter,
                __fsub_rn(__fadd_rn(s_area[i], s_area[j]), inter));
            if (iou > 0.5f) atomicOr(&s_supp[i][j >> 5], 1u << (j & 31));
        }
    }
    __syncthreads();

    // Phase 7: serial greedy keep (inherently sequential; tiny).
    if (tid == 0) {
        unsigned km[4] = {0u, 0u, 0u, 0u};
        for (int k = 0; k < NTOP; ++k)
            if (s_sc[k] >= 0.05f) km[k >> 5] |= 1u << (k & 31);
        for (int i = 0; i < NTOP; ++i) {
            if ((km[i >> 5] >> (i & 31)) & 1u) {
                km[0] &= ~s_supp[i][0];
                km[1] &= ~s_supp[i][1];
                km[2] &= ~s_supp[i][2];
                km[3] &= ~s_supp[i][3];
            }
        }
        s_keep[0] = km[0]; s_keep[1] = km[1]; s_keep[2] = km[2]; s_keep[3] = km[3];
    }
    __syncthreads();

    // Phase 8: outputs, concatenated flattened tuple:
    // boxes [B,100,4] | scores [B,100] | cls [B,100] | keep [B,100], all f32.
    if (tid < NTOP) {
        const float inv = 1.0f / 512.0f;   // power of two: exact
        float b0 = fminf(fmaxf(s_x1[tid], 0.0f), 511.0f) * inv;
        float b1 = fminf(fmaxf(s_y1[tid], 0.0f), 511.0f) * inv;
        float b2 = fminf(fmaxf(s_x2[tid], 0.0f), 511.0f) * inv;
        float b3 = fminf(fmaxf(s_y2[tid], 0.0f), 511.0f) * inv;
        int boff = (b * NTOP + tid) * 4;
        out[boff + 0] = b0;
        out[boff + 1] = b1;
        out[boff + 2] = b2;
        out[boff + 3] = b3;
        out[BATCH * NTOP * 4 + b * NTOP + tid] = s_sc[tid];
        out[BATCH * NTOP * 5 + b * NTOP + tid] = (float)s_cls[tid];
        out[BATCH * NTOP * 6 + b * NTOP + tid] =
            ((s_keep[tid >> 5] >> (tid & 31)) & 1u) ? 1.0f : 0.0f;
    }
}

// ---------------------------------------------------------------------------
extern "C" void kernel_launch(void* const* d_in, const int* in_sizes, int n_in,
                              void* d_out, int out_size) {
    const float* pred   = (const float*)d_in[0];   // (64, 5456, 85) f32
    const float* pixloc = (const float*)d_in[1];   // (5456, 4) f32
    float* out = (float*)d_out;

    static bool configured = false;
    if (!configured) {
        cudaFuncSetAttribute(k_topk_nms,
                             cudaFuncAttributeMaxDynamicSharedMemorySize,
                             SKEYMAX * sizeof(unsigned long long));
        configured = true;
    }

    k_filter<<<BATCH * SEGS, 256>>>(pred);
    k_topk_nms<<<BATCH, 512, SKEYMAX * sizeof(unsigned long long)>>>(
        pred, pixloc, out);
}

// round 11
// speedup vs baseline: 1.9373x; 1.9373x over previous
#include <cuda_runtime.h>

#define BATCH   64
#define HW      5456
#define NCH     85
#define NCLS    80
#define NTOP    100
#define PER_IMG (HW * NCH)        /* 463760 floats per image */
#define T_CAND  2.0f
#define T_CHECK 2.73f
#define FLATMAX 524287            /* 2^19 - 1; flat = c*HW+hw < 436480 */

#define SEGS    16                /* filter blocks per image */
#define SEG_ROWS (HW / SEGS)      /* 341 */
#define SEGCAP  2048              /* smem staging slots per segment */
#define SEGOUT  128               /* per-segment output slots (top-100 fits) */
#define MERGECAP (SEGS * SEGOUT)  /* 2048 keys max in merge kernel */

// Scratch (static device globals). Per-segment buffers written
// unconditionally every launch -> no reset kernel, no global atomics.
__device__ unsigned long long g_cand[BATCH][SEGS * SEGOUT];
__device__ int g_scnt[BATCH][SEGS];
__device__ int g_ssafe[BATCH][SEGS];

// ---------------------------------------------------------------------------
// Bit-exact XLA-style sigmoid: 1 / (1 + expf(-x)), div.rn, no contraction.
__device__ __forceinline__ float xla_sigmoid(float x) {
    return __fdiv_rn(1.0f, __fadd_rn(1.0f, expf(-x)));
}

__device__ __forceinline__ unsigned long long make_key(float score, int flat) {
    // score in (0,1): positive float bits are order-preserving as uint.
    // Larger key = better: score desc, then smaller flat index (class-major).
    return ((unsigned long long)__float_as_uint(score) << 19)
         | (unsigned)(FLATMAX - flat);
}

// ---------------------------------------------------------------------------
// Exact rank-`rank0` (largest) key via 7-pass MSB radix select over unique
// keys in smem. Warp-parallel suffix scan; all threads return the kth key.
template <int NT>
__device__ __forceinline__ unsigned long long radix_select_kth(
    const unsigned long long* keys, int n, int rank0, int tid,
    int* s_hist, int* s_ssum, unsigned long long* s_prefix, int* s_rank)
{
    if (tid == 0) { *s_prefix = 0ULL; *s_rank = rank0; }
    __syncthreads();
    unsigned long long prefix = 0ULL;
    for (int d = 6; d >= 0; --d) {
        int rank = *s_rank;
        if (tid < 256) s_hist[tid] = 0;
        __syncthreads();
        unsigned long long hmask = (~0ULL) << (8 * (d + 1));
        for (int i = tid; i < n; i += NT) {
            unsigned long long k = keys[i];
            if (((k ^ prefix) & hmask) == 0ULL)
                atomicAdd(&s_hist[(int)((k >> (8 * d)) & 255)], 1);
        }
        __syncthreads();
        // s_ssum[v] = sum(hist[v..255]) via one warp.
        if (tid < 32) {
            int loc[8]; int sum = 0;
            #pragma unroll
            for (int j = 0; j < 8; ++j) {
                sum += s_hist[255 - (tid * 8 + j)];
                loc[j] = sum;
            }
            int inc = sum;
            #pragma unroll
            for (int dd = 1; dd < 32; dd <<= 1) {
                int y = __shfl_up_sync(0xFFFFFFFFu, inc, dd);
                if (tid >= dd) inc += y;
            }
            int excl = inc - sum;
            #pragma unroll
            for (int j = 0; j < 8; ++j)
                s_ssum[255 - (tid * 8 + j)] = excl + loc[j];
        }
        __syncthreads();
        if (tid < 256) {
            int above = (tid < 255) ? s_ssum[tid + 1] : 0;
            if (s_ssum[tid] >= rank && above < rank) {   // unique winner
                *s_rank = rank - above;
                *s_prefix = prefix | ((unsigned long long)tid << (8 * d));
            }
        }
        __syncthreads();
        prefix = *s_prefix;
    }
    return prefix;
}

// ---------------------------------------------------------------------------
// Kernel 1: stream logits (4-row-batched loads, no transcendentals in the hot
// loop), stage raw candidates + per-row nks in smem; then score ONLY the
// compacted candidates (dense per-lane powf); then per-segment exact top-100
// radix pre-selection. One deterministic output range per block.
__global__ void __launch_bounds__(256) k_filter(const float* __restrict__ pred) {
    __shared__ unsigned long long s_buf[SEGCAP];   // raw then scored keys
    __shared__ float s_nks[SEG_ROWS];              // nks logit per local row
    __shared__ int s_hist[256], s_ssum[256];
    __shared__ unsigned long long s_prefixv;
    __shared__ int s_rankv;
    __shared__ int s_cnt, s_safe, s_out;

    const int b    = blockIdx.x / SEGS;
    const int seg  = blockIdx.x % SEGS;
    const int lane = threadIdx.x & 31;
    const int warp = threadIdx.x >> 5;
    const int tid  = threadIdx.x;

    if (tid == 0) { s_cnt = 0; s_safe = 0; s_out = 0; }
    __syncthreads();

    const int lr0 = warp * 43;
    const int lr1 = min(lr0 + 43, SEG_ROWS);
    const float* imgBase = pred + (size_t)b * PER_IMG;

    int safeAcc = 0;

    // Per-row processing (compaction only; no transcendentals).
    auto process_row = [&](float v0, float v1, float v2, int lr) {
        const int hw = seg * SEG_ROWS + lr;
        if (lane == 20) s_nks[lr] = v2;            // channel 84 logit
        bool p0 = v0 >= T_CAND;
        bool p1 = v1 >= T_CAND;
        bool p2 = (lane < 16) && (v2 >= T_CAND);   // only ch 64..79 are cls
        unsigned m0 = __ballot_sync(0xFFFFFFFFu, p0);
        unsigned m1 = __ballot_sync(0xFFFFFFFFu, p1);
        unsigned m2 = __ballot_sync(0xFFFFFFFFu, p2);
        if (m0 | m1 | m2) {
            int tot = __popc(m0) + __popc(m1) + __popc(m2);
            int base;
            if (lane == 0) base = atomicAdd(&s_cnt, tot);
            base = __shfl_sync(0xFFFFFFFFu, base, 0);
            unsigned lt = (1u << lane) - 1u;
            if (p0) {
                int o = base + __popc(m0 & lt);
                if (o < SEGCAP)
                    s_buf[o] = ((unsigned long long)__float_as_uint(v0) << 32)
                             | (unsigned)(lane * HW + hw);
            }
            int b1 = base + __popc(m0);
            if (p1) {
                int o = b1 + __popc(m1 & lt);
                if (o < SEGCAP)
                    s_buf[o] = ((unsigned long long)__float_as_uint(v1) << 32)
                             | (unsigned)((lane + 32) * HW + hw);
            }
            int b2 = b1 + __popc(m1);
            if (p2) {
                int o = b2 + __popc(m2 & lt);
                if (o < SEGCAP)
                    s_buf[o] = ((unsigned long long)__float_as_uint(v2) << 32)
                             | (unsigned)((lane + 64) * HW + hw);
            }
            safeAcc += (int)(p0 && v0 >= T_CHECK)
                     + (int)(p1 && v1 >= T_CHECK)
                     + (int)(p2 && v2 >= T_CHECK);
        }
    };

    // Phase A: 4-row unrolled streaming (12 loads in flight before ballots).
    int lr = lr0;
    for (; lr + 4 <= lr1; lr += 4) {
        float a0[4], a1[4], a2[4];
        #pragma unroll
        for (int u = 0; u < 4; ++u) {
            const float* row = imgBase + (size_t)(seg * SEG_ROWS + lr + u) * NCH;
            a0[u] = row[lane];
            a1[u] = row[lane + 32];
            a2[u] = (lane < 21) ? row[lane + 64] : -1e30f;
        }
        #pragma unroll
        for (int u = 0; u < 4; ++u)
            process_row(a0[u], a1[u], a2[u], lr + u);
    }
    for (; lr < lr1; ++lr) {
        const float* row = imgBase + (size_t)(seg * SEG_ROWS + lr) * NCH;
        float v0 = row[lane];
        float v1 = row[lane + 32];
        float v2 = (lane < 21) ? row[lane + 64] : -1e30f;
        process_row(v0, v1, v2, lr);
    }

    {   // warp-reduce safe count -> one smem atomic per warp
        int s = safeAcc;
        s += __shfl_xor_sync(0xFFFFFFFFu, s, 16);
        s += __shfl_xor_sync(0xFFFFFFFFu, s, 8);
        s += __shfl_xor_sync(0xFFFFFFFFu, s, 4);
        s += __shfl_xor_sync(0xFFFFFFFFu, s, 2);
        s += __shfl_xor_sync(0xFFFFFFFFu, s, 1);
        if (lane == 0 && s) atomicAdd(&s_safe, s);
    }
    __syncthreads();

    const int  n        = min(s_cnt, SEGCAP);
    const bool overflow = (s_cnt > SEGCAP);

    // Phase B: score ONLY compacted candidates (dense, per-lane SIMD powf).
    for (int i = tid; i < n; i += 256) {
        unsigned long long cd = s_buf[i];
        unsigned flat = (unsigned)(cd & 0xFFFFFFFFu);
        float x = __uint_as_float((unsigned)(cd >> 32));
        int hw = (int)(flat % HW);
        float e = __fsub_rn(2.0f, xla_sigmoid(s_nks[hw - seg * SEG_ROWS]));
        float sc = powf(xla_sigmoid(x), e);
        s_buf[i] = make_key(sc, (int)flat);
    }
    __syncthreads();

    // Phase C: per-segment exact top-100 (keys unique -> exact), write out.
    unsigned long long* dst = &g_cand[b][seg * SEGOUT];
    int outc;
    if (overflow) {
        outc = -1;                                  // merge kernel -> fallback
    } else if (n <= NTOP) {
        for (int i = tid; i < n; i += 256) dst[i] = s_buf[i];
        outc = n;
    } else {
        unsigned long long kth = radix_select_kth<256>(
            s_buf, n, NTOP, tid, s_hist, s_ssum, &s_prefixv, &s_rankv);
        for (int i = tid; i < n; i += 256) {
            unsigned long long k = s_buf[i];
            if (k >= kth) dst[atomicAdd(&s_out, 1)] = k;   // exactly 100
        }
        outc = NTOP;
    }
    if (tid == 0) {
        g_scnt[b][seg]  = outc;
        g_ssafe[b][seg] = s_safe;
    }
}

// ---------------------------------------------------------------------------
// Kernel 2: one block per image merges <=1600 pre-selected keys: radix-select
// the exact 100th, sort top-100, decode boxes, class-aware NMS, write.
__global__ void __launch_bounds__(512) k_topk_nms(const float* __restrict__ pred,
                                                  const float* __restrict__ pixloc,
                                                  float* __restrict__ out) {
    const int b = blockIdx.x;
    const int tid = threadIdx.x;
    const int NT = 512;
    const int lane = tid & 31;
    const int warp = tid >> 5;

    __shared__ unsigned long long s_keys[MERGECAP];   // 16 KB
    __shared__ int s_hist[256], s_ssum[256];
    __shared__ int s_c[SEGS], s_off[SEGS];
    __shared__ unsigned long long s_prefixv;
    __shared__ int s_rankv, s_n, s_cnt;
    __shared__ unsigned long long s_top[128];
    __shared__ float s_x1[NTOP], s_y1[NTOP], s_x2[NTOP], s_y2[NTOP];
    __shared__ float s_area[NTOP], s_sc[NTOP];
    __shared__ int s_cls[NTOP];
    __shared__ unsigned s_supp[NTOP][4];
    __shared__ unsigned s_keep[4];

    const float* base = pred + (size_t)b * PER_IMG;

    if (tid < SEGS) s_c[tid] = g_scnt[b][tid];
    __syncthreads();

    if (tid == 0) {
        int total = 0, safe = 0;
        bool bad = false;
        for (int s = 0; s < SEGS; ++s) {
            int c = s_c[s];
            if (c < 0) bad = true;
            s_off[s] = total;
            total += max(c, 0);
            safe += g_ssafe[b][s];
        }
        if (!bad && total >= NTOP && safe >= NTOP) {
            s_n = total;
        } else {
            // Brute-force fallback (correct for any data; never expected).
            unsigned long long best[NTOP];
            int nb = 0, minidx = 0;
            unsigned long long minkey = 0;
            for (int hw = 0; hw < HW; ++hw) {
                float e = __fsub_rn(2.0f, xla_sigmoid(base[hw * NCH + NCLS + 4]));
                for (int c = 0; c < NCLS; ++c) {
                    float s = xla_sigmoid(base[hw * NCH + c]);
                    if (nb == NTOP &&
                        __float_as_uint(s) < (unsigned)(minkey >> 19)) continue;
                    float sc = powf(s, e);
                    unsigned long long key = make_key(sc, c * HW + hw);
                    if (nb < NTOP) {
                        best[nb++] = key;
                        if (nb == NTOP) {
                            minkey = best[0]; minidx = 0;
                            for (int i = 1; i < NTOP; ++i)
                                if (best[i] < minkey) { minkey = best[i]; minidx = i; }
                        }
                    } else if (key > minkey) {
                        best[minidx] = key;
                        minkey = best[0]; minidx = 0;
                        for (int i = 1; i < NTOP; ++i)
                            if (best[i] < minkey) { minkey = best[i]; minidx = i; }
                    }
                }
            }
            for (int i = 0; i < NTOP; ++i) s_keys[i] = best[i];
            s_n = -NTOP;   // negative => keys already staged in s_keys
        }
        s_cnt = 0;
    }
    __syncthreads();

    int n = s_n;
    if (n >= 0) {
        // Stage keys: one warp per segment (16 warps = 512 threads).
        if (warp < SEGS) {
            int c = s_c[warp], off = s_off[warp];
            const unsigned long long* src = &g_cand[b][warp * SEGOUT];
            for (int i = lane; i < c; i += 32) s_keys[off + i] = src[i];
        }
    } else {
        n = -n;
    }
    __syncthreads();

    // Exact 100th-largest key over <=1600 unique keys.
    unsigned long long kth = radix_select_kth<512>(
        s_keys, n, NTOP, tid, s_hist, s_ssum, &s_prefixv, &s_rankv);

    // Compact the exactly-100 keys >= kth.
    for (int i = tid; i < n; i += NT) {
        unsigned long long k = s_keys[i];
        if (k >= kth) {
            int p = atomicAdd(&s_cnt, 1);
            if (p < 128) s_top[p] = k;
        }
    }
    __syncthreads();
    if (tid < 128 && tid >= s_cnt) s_top[tid] = 0ULL;
    __syncthreads();

    // Bitonic sort 128 keys descending.
    for (int k = 2; k <= 128; k <<= 1) {
        for (int j = k >> 1; j > 0; j >>= 1) {
            if (tid < 128) {
                int ixj = tid ^ j;
                if (ixj > tid) {
                    unsigned long long a = s_top[tid], c = s_top[ixj];
                    bool up = (tid & k) == 0;  // descending
                    if (up ? (a < c) : (a > c)) { s_top[tid] = c; s_top[ixj] = a; }
                }
            }
            __syncthreads();
        }
    }

    // Decode boxes for the top-100 (bit-exact: no FMA contraction).
    if (tid < NTOP) {
        unsigned long long key = s_top[tid];
        int flat = FLATMAX - (int)(key & 0x7FFFF);
        int c = flat / HW;
        int hw = flat - c * HW;
        float sc = __uint_as_float((unsigned)(key >> 19));
        const float* rp = base + hw * NCH;
        float e0 = expf(rp[80]);
        float e1 = expf(rp[81]);
        float e2 = expf(rp[82]);
        float e3 = expf(rp[83]);
        float x1 = __fadd_rn(__fmul_rn(e0, -1.0f), pixloc[4 * hw + 0]);
        float y1 = __fadd_rn(__fmul_rn(e1, -1.0f), pixloc[4 * hw + 1]);
        float x2 = __fadd_rn(__fmul_rn(e2,  1.0f), pixloc[4 * hw + 2]);
        float y2 = __fadd_rn(__fmul_rn(e3,  1.0f), pixloc[4 * hw + 3]);
        s_x1[tid] = x1; s_y1[tid] = y1; s_x2[tid] = x2; s_y2[tid] = y2;
        s_area[tid] = __fmul_rn(__fsub_rn(x2, x1), __fsub_rn(y2, y1));
        s_sc[tid] = sc;
        s_cls[tid] = c;
    }
    if (tid < NTOP * 4) ((unsigned*)s_supp)[tid] = 0u;
    __syncthreads();

    // Suppress matrix (iou > 0.5, same class, j later than i).
    for (int p = tid; p < NTOP * NTOP; p += NT) {
        int i = p / NTOP, j = p - i * NTOP;
        if (j > i && s_cls[i] == s_cls[j]) {
            float xx1 = fmaxf(s_x1[i], s_x1[j]);
            float yy1 = fmaxf(s_y1[i], s_y1[j]);
            float xx2 = fminf(s_x2[i], s_x2[j]);
            float yy2 = fminf(s_y2[i], s_y2[j]);
            float w = fmaxf(1e-28f, __fsub_rn(xx2, xx1));
            float h = fmaxf(1e-28f, __fsub_rn(yy2, yy1));
            float inter = __fmul_rn(w, h);
            float iou = __fdiv_rn(inter,
                __fsub_rn(__fadd_rn(s_area[i], s_area[j]), inter));
            if (iou > 0.5f) atomicOr(&s_supp[i][j >> 5], 1u << (j & 31));
        }
    }
    __syncthreads();

    // Serial greedy keep (inherently sequential; tiny).
    if (tid == 0) {
        unsigned km[4] = {0u, 0u, 0u, 0u};
        for (int k = 0; k < NTOP; ++k)
            if (s_sc[k] >= 0.05f) km[k >> 5] |= 1u << (k & 31);
        for (int i = 0; i < NTOP; ++i) {
            if ((km[i >> 5] >> (i & 31)) & 1u) {
                km[0] &= ~s_supp[i][0];
                km[1] &= ~s_supp[i][1];
                km[2] &= ~s_supp[i][2];
                km[3] &= ~s_supp[i][3];
            }
        }
        s_keep[0] = km[0]; s_keep[1] = km[1]; s_keep[2] = km[2]; s_keep[3] = km[3];
    }
    __syncthreads();

    // Outputs, concatenated flattened tuple:
    // boxes [B,100,4] | scores [B,100] | cls [B,100] | keep [B,100], all f32.
    if (tid < NTOP) {
        const float inv = 1.0f / 512.0f;   // power of two: exact
        float b0 = fminf(fmaxf(s_x1[tid], 0.0f), 511.0f) * inv;
        float b1 = fminf(fmaxf(s_y1[tid], 0.0f), 511.0f) * inv;
        float b2 = fminf(fmaxf(s_x2[tid], 0.0f), 511.0f) * inv;
        float b3 = fminf(fmaxf(s_y2[tid], 0.0f), 511.0f) * inv;
        int boff = (b * NTOP + tid) * 4;
        out[boff + 0] = b0;
        out[boff + 1] = b1;
        out[boff + 2] = b2;
        out[boff + 3] = b3;
        out[BATCH * NTOP * 4 + b * NTOP + tid] = s_sc[tid];
        out[BATCH * NTOP * 5 + b * NTOP + tid] = (float)s_cls[tid];
        out[BATCH * NTOP * 6 + b * NTOP + tid] =
            ((s_keep[tid >> 5] >> (tid & 31)) & 1u) ? 1.0f : 0.0f;
    }
}

// ---------------------------------------------------------------------------
extern "C" void kernel_launch(void* const* d_in, const int* in_sizes, int n_in,
                              void* d_out, int out_size) {
    const float* pred   = (const float*)d_in[0];   // (64, 5456, 85) f32
    const float* pixloc = (const float*)d_in[1];   // (5456, 4) f32
    float* out = (float*)d_out;

    k_filter<<<BATCH * SEGS, 256>>>(pred);
    k_topk_nms<<<BATCH, 512>>>(pred, pixloc, out);
}

// round 12
// speedup vs baseline: 2.1114x; 1.0899x over previous
#include <cuda_runtime.h>

#define BATCH   64
#define HW      5456
#define NCH     85
#define NCLS    80
#define NTOP    100
#define PER_IMG (HW * NCH)        /* 463760 floats per image */
#define T_CAND  2.0f
#define T_CHECK 2.73f
#define FLATMAX 524287            /* 2^19 - 1; flat = c*HW+hw < 436480 */

#define SEGS    16                /* filter blocks per image */
#define SEG_ROWS (HW / SEGS)      /* 341 */
#define SEGCAP  2048              /* smem staging slots per segment */
#define SEGOUT  128               /* per-segment output slots (top-100 fits) */
#define MERGECAP (SEGS * SEGOUT)  /* 2048 keys max in merge kernel */

typedef unsigned long long ull;

// Scratch (static device globals). Per-segment buffers written
// unconditionally every launch -> no reset kernel, no global atomics.
__device__ ull g_cand[BATCH][SEGS * SEGOUT];
__device__ ull g_skth[BATCH][SEGS];     // segment's exact 100th key (0 if <100)
__device__ int g_scnt[BATCH][SEGS];
__device__ int g_ssafe[BATCH][SEGS];

// ---------------------------------------------------------------------------
// Bit-exact XLA-style sigmoid: 1 / (1 + expf(-x)), div.rn, no contraction.
__device__ __forceinline__ float xla_sigmoid(float x) {
    return __fdiv_rn(1.0f, __fadd_rn(1.0f, expf(-x)));
}

__device__ __forceinline__ ull make_key(float score, int flat) {
    // score in (0,1): positive float bits are order-preserving as uint.
    // Larger key = better: score desc, then smaller flat index (class-major).
    return ((ull)__float_as_uint(score) << 19) | (unsigned)(FLATMAX - flat);
}

// ---------------------------------------------------------------------------
// Exact rank-`rank0` (largest) key via 7-pass MSB radix select over unique
// keys in smem. Suffix scan AND winner selection live in warp 0's registers:
// lane t, chunk j holds ssum[v]=excl+loc[j] and ssum[v+1]=j?excl+loc[j-1]:excl
// so the unique (val>=rank && above<rank) winner updates rank/prefix directly.
template <int NT>
__device__ __forceinline__ ull radix_select_kth(
    const ull* keys, int n, int rank0, int tid,
    int* s_hist, ull* s_prefix, int* s_rank)
{
    if (tid == 0) { *s_prefix = 0ULL; *s_rank = rank0; }
    __syncthreads();
    ull prefix = 0ULL;
    for (int d = 6; d >= 0; --d) {
        if (tid < 256) s_hist[tid] = 0;
        __syncthreads();
        ull hmask = (~0ULL) << (8 * (d + 1));
        for (int i = tid; i < n; i += NT) {
            ull k = keys[i];
            if (((k ^ prefix) & hmask) == 0ULL)
                atomicAdd(&s_hist[(int)((k >> (8 * d)) & 255)], 1);
        }
        __syncthreads();
        if (tid < 32) {
            int rank = *s_rank;
            int loc[8]; int sum = 0;
            #pragma unroll
            for (int j = 0; j < 8; ++j) {
                sum += s_hist[255 - (tid * 8 + j)];
                loc[j] = sum;
            }
            int inc = sum;
            #pragma unroll
            for (int dd = 1; dd < 32; dd <<= 1) {
                int y = __shfl_up_sync(0xFFFFFFFFu, inc, dd);
                if (tid >= dd) inc += y;
            }
            int excl = inc - sum;
            #pragma unroll
            for (int j = 0; j < 8; ++j) {
                int val   = excl + loc[j];
                int above = j ? (excl + loc[j - 1]) : excl;
                if (val >= rank && above < rank) {      // unique winner lane/j
                    *s_rank = rank - above;
                    *s_prefix = prefix
                              | ((ull)(255 - (tid * 8 + j)) << (8 * d));
                }
            }
        }
        __syncthreads();
        prefix = *s_prefix;
    }
    return prefix;
}

// ---------------------------------------------------------------------------
// Kernel 1: stream logits (4-row-batched loads; hot loop has NO ballots and
// no transcendentals -- per-candidate predicated atomics are REDUX-aggregated
// by ptxas). Then score only the compacted candidates; then per-segment exact
// top-100 radix pre-selection + the segment's kth key for merge-time pruning.
__global__ void __launch_bounds__(256) k_filter(const float* __restrict__ pred) {
    __shared__ ull s_buf[SEGCAP];     // raw then scored keys
    __shared__ float s_nks[SEG_ROWS]; // nks logit per local row
    __shared__ int s_hist[256];
    __shared__ ull s_prefixv;
    __shared__ int s_rankv;
    __shared__ int s_cnt, s_safe, s_out;

    const int b    = blockIdx.x / SEGS;
    const int seg  = blockIdx.x % SEGS;
    const int lane = threadIdx.x & 31;
    const int warp = threadIdx.x >> 5;
    const int tid  = threadIdx.x;

    if (tid == 0) { s_cnt = 0; s_safe = 0; s_out = 0; }
    __syncthreads();

    const int lr0 = warp * 43;
    const int lr1 = min(lr0 + 43, SEG_ROWS);
    const float* imgBase = pred + (size_t)b * PER_IMG;

    int safeAcc = 0;

    // Per-row: 3 compares + rare aggregated-atomic append. No ballots.
    auto process_row = [&](float v0, float v1, float v2, int lr) {
        const int hw = seg * SEG_ROWS + lr;
        if (lane == 20) s_nks[lr] = v2;            // channel 84 logit
        if (v0 >= T_CAND) {
            int o = atomicAdd(&s_cnt, 1);
            if (o < SEGCAP)
                s_buf[o] = ((ull)__float_as_uint(v0) << 32)
                         | (unsigned)(lane * HW + hw);
        }
        if (v1 >= T_CAND) {
            int o = atomicAdd(&s_cnt, 1);
            if (o < SEGCAP)
                s_buf[o] = ((ull)__float_as_uint(v1) << 32)
                         | (unsigned)((lane + 32) * HW + hw);
        }
        if ((lane < 16) && (v2 >= T_CAND)) {
            int o = atomicAdd(&s_cnt, 1);
            if (o < SEGCAP)
                s_buf[o] = ((ull)__float_as_uint(v2) << 32)
                         | (unsigned)((lane + 64) * HW + hw);
        }
        safeAcc += (int)(v0 >= T_CHECK) + (int)(v1 >= T_CHECK)
                 + (int)((lane < 16) && (v2 >= T_CHECK));
    };

    // Phase A: 4-row unrolled streaming (12 loads in flight).
    int lr = lr0;
    for (; lr + 4 <= lr1; lr += 4) {
        float a0[4], a1[4], a2[4];
        #pragma unroll
        for (int u = 0; u < 4; ++u) {
            const float* row = imgBase + (size_t)(seg * SEG_ROWS + lr + u) * NCH;
            a0[u] = row[lane];
            a1[u] = row[lane + 32];
            a2[u] = (lane < 21) ? row[lane + 64] : -1e30f;
        }
        #pragma unroll
        for (int u = 0; u < 4; ++u)
            process_row(a0[u], a1[u], a2[u], lr + u);
    }
    for (; lr < lr1; ++lr) {
        const float* row = imgBase + (size_t)(seg * SEG_ROWS + lr) * NCH;
        float v0 = row[lane];
        float v1 = row[lane + 32];
        float v2 = (lane < 21) ? row[lane + 64] : -1e30f;
        process_row(v0, v1, v2, lr);
    }

    {   // warp-reduce safe count -> one smem atomic per warp
        int s = safeAcc;
        s += __shfl_xor_sync(0xFFFFFFFFu, s, 16);
        s += __shfl_xor_sync(0xFFFFFFFFu, s, 8);
        s += __shfl_xor_sync(0xFFFFFFFFu, s, 4);
        s += __shfl_xor_sync(0xFFFFFFFFu, s, 2);
        s += __shfl_xor_sync(0xFFFFFFFFu, s, 1);
        if (lane == 0 && s) atomicAdd(&s_safe, s);
    }
    __syncthreads();

    const int  n        = min(s_cnt, SEGCAP);
    const bool overflow = (s_cnt > SEGCAP);

    // Phase B: score ONLY compacted candidates (dense, per-lane SIMD powf).
    for (int i = tid; i < n; i += 256) {
        ull cd = s_buf[i];
        unsigned flat = (unsigned)(cd & 0xFFFFFFFFu);
        float x = __uint_as_float((unsigned)(cd >> 32));
        int hw = (int)(flat % HW);
        float e = __fsub_rn(2.0f, xla_sigmoid(s_nks[hw - seg * SEG_ROWS]));
        float sc = powf(xla_sigmoid(x), e);
        s_buf[i] = make_key(sc, (int)flat);
    }
    __syncthreads();

    // Phase C: per-segment exact top-100 (keys unique -> exact), write out.
    ull* dst = &g_cand[b][seg * SEGOUT];
    int outc;
    ull kth = 0ULL;
    if (overflow) {
        outc = -1;                                  // merge kernel -> fallback
    } else if (n <= NTOP) {
        for (int i = tid; i < n; i += 256) dst[i] = s_buf[i];
        outc = n;
    } else {
        kth = radix_select_kth<256>(s_buf, n, NTOP, tid,
                                    s_hist, &s_prefixv, &s_rankv);
        for (int i = tid; i < n; i += 256) {
            ull k = s_buf[i];
            if (k >= kth) dst[atomicAdd(&s_out, 1)] = k;   // exactly 100
        }
        outc = NTOP;
    }
    if (tid == 0) {
        g_scnt[b][seg]  = outc;
        g_ssafe[b][seg] = s_safe;
        g_skth[b][seg]  = (outc == NTOP) ? kth : 0ULL;
    }
}

// ---------------------------------------------------------------------------
// Kernel 2: one block per image merges the pre-selected keys. Staging prunes
// with bound = max over segments of that segment's 100th key (exact: the
// argmax segment alone contributes 100 keys >= bound, so the global 100th
// >= bound and every global-top-100 key survives the prune).
__global__ void __launch_bounds__(512) k_topk_nms(const float* __restrict__ pred,
                                                  const float* __restrict__ pixloc,
                                                  float* __restrict__ out) {
    const int b = blockIdx.x;
    const int tid = threadIdx.x;
    const int NT = 512;
    const int lane = tid & 31;
    const int warp = tid >> 5;

    __shared__ ull s_keys[MERGECAP];   // 16 KB
    __shared__ int s_hist[256];
    __shared__ int s_c[SEGS];
    __shared__ ull s_prefixv, s_bound;
    __shared__ int s_rankv, s_n, s_cnt, s_nstage;
    __shared__ int s_total, s_safeT, s_bad;
    __shared__ ull s_top[128];
    __shared__ float s_x1[NTOP], s_y1[NTOP], s_x2[NTOP], s_y2[NTOP];
    __shared__ float s_area[NTOP], s_sc[NTOP];
    __shared__ int s_cls[NTOP];
    __shared__ unsigned s_supp[NTOP][4];
    __shared__ unsigned s_keep[4];

    const float* base = pred + (size_t)b * PER_IMG;

    // Parallel prologue: 16 lanes load counts/safe/kth; warp-reduce.
    if (tid < 32) {
        int  c  = (tid < SEGS) ? g_scnt[b][tid]  : 0;
        int  sf = (tid < SEGS) ? g_ssafe[b][tid] : 0;
        ull  kq = (tid < SEGS) ? g_skth[b][tid]  : 0ULL;
        if (tid < SEGS) s_c[tid] = c;
        int bad = (c < 0) ? 1 : 0;
        int cc  = max(c, 0);
        #pragma unroll
        for (int d = 16; d; d >>= 1) {
            cc  += __shfl_xor_sync(0xFFFFFFFFu, cc, d);
            sf  += __shfl_xor_sync(0xFFFFFFFFu, sf, d);
            bad |= __shfl_xor_sync(0xFFFFFFFFu, bad, d);
            ull o = __shfl_xor_sync(0xFFFFFFFFu, kq, d);
            kq = (o > kq) ? o : kq;
        }
        if (tid == 0) {
            s_total = cc; s_safeT = sf; s_bad = bad; s_bound = kq;
            s_cnt = 0; s_nstage = 0;
        }
    }
    __syncthreads();

    if (tid == 0) {
        if (!s_bad && s_total >= NTOP && s_safeT >= NTOP) {
            s_n = s_total;
        } else {
            // Brute-force fallback (correct for any data; never expected).
            ull best[NTOP];
            int nb = 0, minidx = 0;
            ull minkey = 0;
            for (int hw = 0; hw < HW; ++hw) {
                float e = __fsub_rn(2.0f, xla_sigmoid(base[hw * NCH + NCLS + 4]));
                for (int c = 0; c < NCLS; ++c) {
                    float s = xla_sigmoid(base[hw * NCH + c]);
                    if (nb == NTOP &&
                        __float_as_uint(s) < (unsigned)(minkey >> 19)) continue;
                    float sc = powf(s, e);
                    ull key = make_key(sc, c * HW + hw);
                    if (nb < NTOP) {
                        best[nb++] = key;
                        if (nb == NTOP) {
                            minkey = best[0]; minidx = 0;
                            for (int i = 1; i < NTOP; ++i)
                                if (best[i] < minkey) { minkey = best[i]; minidx = i; }
                        }
                    } else if (key > minkey) {
                        best[minidx] = key;
                        minkey = best[0]; minidx = 0;
                        for (int i = 1; i < NTOP; ++i)
                            if (best[i] < minkey) { minkey = best[i]; minidx = i; }
                    }
                }
            }
            for (int i = 0; i < NTOP; ++i) s_keys[i] = best[i];
            s_n = -NTOP;   // negative => 100 keys already staged
        }
    }
    __syncthreads();

    int nkeys;
    if (s_n >= 0) {
        // Stage keys >= bound (order-free atomic positions); warp per segment.
        ull bound = s_bound;
        if (warp < SEGS) {
            int c = s_c[warp];
            const ull* src = &g_cand[b][warp * SEGOUT];
            for (int i = lane; i < c; i += 32) {
                ull k = src[i];
                if (k >= bound) {
                    int p = atomicAdd(&s_nstage, 1);
                    s_keys[p] = k;
                }
            }
        }
        __syncthreads();
        nkeys = s_nstage;
    } else {
        nkeys = NTOP;
        __syncthreads();
    }

    // Exact 100th-largest key over the (pruned) unique keys.
    ull kth = radix_select_kth<512>(s_keys, nkeys, NTOP, tid,
                                    s_hist, &s_prefixv, &s_rankv);

    // Compact the exactly-100 keys >= kth.
    for (int i = tid; i < nkeys; i += NT) {
        ull k = s_keys[i];
        if (k >= kth) {
            int p = atomicAdd(&s_cnt, 1);
            if (p < 128) s_top[p] = k;
        }
    }
    __syncthreads();
    if (tid < 128 && tid >= s_cnt) s_top[tid] = 0ULL;
    __syncthreads();

    // Bitonic sort 128 keys descending.
    for (int k = 2; k <= 128; k <<= 1) {
        for (int j = k >> 1; j > 0; j >>= 1) {
            if (tid < 128) {
                int ixj = tid ^ j;
                if (ixj > tid) {
                    ull a = s_top[tid], c = s_top[ixj];
                    bool up = (tid & k) == 0;  // descending
                    if (up ? (a < c) : (a > c)) { s_top[tid] = c; s_top[ixj] = a; }
                }
            }
            __syncthreads();
        }
    }

    // Decode boxes for the top-100 (bit-exact: no FMA contraction).
    if (tid < NTOP) {
        ull key = s_top[tid];
        int flat = FLATMAX - (int)(key & 0x7FFFF);
        int c = flat / HW;
        int hw = flat - c * HW;
        float sc = __uint_as_float((unsigned)(key >> 19));
        const float* rp = base + hw * NCH;
        float e0 = expf(rp[80]);
        float e1 = expf(rp[81]);
        float e2 = expf(rp[82]);
        float e3 = expf(rp[83]);
        float x1 = __fadd_rn(__fmul_rn(e0, -1.0f), pixloc[4 * hw + 0]);
        float y1 = __fadd_rn(__fmul_rn(e1, -1.0f), pixloc[4 * hw + 1]);
        float x2 = __fadd_rn(__fmul_rn(e2,  1.0f), pixloc[4 * hw + 2]);
        float y2 = __fadd_rn(__fmul_rn(e3,  1.0f), pixloc[4 * hw + 3]);
        s_x1[tid] = x1; s_y1[tid] = y1; s_x2[tid] = x2; s_y2[tid] = y2;
        s_area[tid] = __fmul_rn(__fsub_rn(x2, x1), __fsub_rn(y2, y1));
        s_sc[tid] = sc;
        s_cls[tid] = c;
    }
    if (tid < NTOP * 4) ((unsigned*)s_supp)[tid] = 0u;
    __syncthreads();

    // Suppress matrix (iou > 0.5, same class, j later than i).
    for (int p = tid; p < NTOP * NTOP; p += NT) {
        int i = p / NTOP, j = p - i * NTOP;
        if (j > i && s_cls[i] == s_cls[j]) {
            float xx1 = fmaxf(s_x1[i], s_x1[j]);
            float yy1 = fmaxf(s_y1[i], s_y1[j]);
            float xx2 = fminf(s_x2[i], s_x2[j]);
            float yy2 = fminf(s_y2[i], s_y2[j]);
            float w = fmaxf(1e-28f, __fsub_rn(xx2, xx1));
            float h = fmaxf(1e-28f, __fsub_rn(yy2, yy1));
            float inter = __fmul_rn(w, h);
            float iou = __fdiv_rn(inter,
                __fsub_rn(__fadd_rn(s_area[i], s_area[j]), inter));
            if (iou > 0.5f) atomicOr(&s_supp[i][j >> 5], 1u << (j & 31));
        }
    }
    __syncthreads();

    // Serial greedy keep (inherently sequential; tiny).
    if (tid == 0) {
        unsigned km[4] = {0u, 0u, 0u, 0u};
        for (int k = 0; k < NTOP; ++k)
            if (s_sc[k] >= 0.05f) km[k >> 5] |= 1u << (k & 31);
        for (int i = 0; i < NTOP; ++i) {
            if ((km[i >> 5] >> (i & 31)) & 1u) {
                km[0] &= ~s_supp[i][0];
                km[1] &= ~s_supp[i][1];
                km[2] &= ~s_supp[i][2];
                km[3] &= ~s_supp[i][3];
            }
        }
        s_keep[0] = km[0]; s_keep[1] = km[1]; s_keep[2] = km[2]; s_keep[3] = km[3];
    }
    __syncthreads();

    // Outputs, concatenated flattened tuple:
    // boxes [B,100,4] | scores [B,100] | cls [B,100] | keep [B,100], all f32.
    if (tid < NTOP) {
        const float inv = 1.0f / 512.0f;   // power of two: exact
        float b0 = fminf(fmaxf(s_x1[tid], 0.0f), 511.0f) * inv;
        float b1 = fminf(fmaxf(s_y1[tid], 0.0f), 511.0f) * inv;
        float b2 = fminf(fmaxf(s_x2[tid], 0.0f), 511.0f) * inv;
        float b3 = fminf(fmaxf(s_y2[tid], 0.0f), 511.0f) * inv;
        int boff = (b * NTOP + tid) * 4;
        out[boff + 0] = b0;
        out[boff + 1] = b1;
        out[boff + 2] = b2;
        out[boff + 3] = b3;
        out[BATCH * NTOP * 4 + b * NTOP + tid] = s_sc[tid];
        out[BATCH * NTOP * 5 + b * NTOP + tid] = (float)s_cls[tid];
        out[BATCH * NTOP * 6 + b * NTOP + tid] =
            ((s_keep[tid >> 5] >> (tid & 31)) & 1u) ? 1.0f : 0.0f;
    }
}

// ---------------------------------------------------------------------------
extern "C" void kernel_launch(void* const* d_in, const int* in_sizes, int n_in,
                              void* d_out, int out_size) {
    const float* pred   = (const float*)d_in[0];   // (64, 5456, 85) f32
    const float* pixloc = (const float*)d_in[1];   // (5456, 4) f32
    float* out = (float*)d_out;

    k_filter<<<BATCH * SEGS, 256>>>(pred);
    k_topk_nms<<<BATCH, 512>>>(pred, pixloc, out);
}